// round 2
// baseline (speedup 1.0000x reference)
#include <cuda_runtime.h>

#define NN 50000
#define EE 800000
#define ET (EE + NN)
#define HEADS 4
#define HID 64
#define C1 256   /* HEADS*HID */
#define C2 64
#define NEG 0.2f

// ---------------- scratch (device globals; no cudaMalloc allowed) -------------
__device__ __align__(16) float g_h1[(size_t)NN * C1];     // x@W1
__device__ __align__(16) float g_als1[NN * HEADS];
__device__ __align__(16) float g_ald1[NN * HEADS];
__device__ __align__(16) float g_h2[(size_t)NN * C1];     // elu(agg1 + b1)
__device__ __align__(16) float g_h2lin[(size_t)NN * C2];  // h2@W2
__device__ float g_als2[NN];
__device__ float g_ald2[NN];
__device__ int   g_cnt[NN];
__device__ int   g_off[NN + 1];
__device__ int   g_cur[NN];
__device__ int   g_psrc[ET];

__device__ __forceinline__ float lrelu(float x) { return x > 0.f ? x : NEG * x; }
__device__ __forceinline__ float elu_f(float x) { return x > 0.f ? x : __expf(x) - 1.f; }

// ---------------- CSR build ---------------------------------------------------
__global__ void k_init() {
  int i = blockIdx.x * blockDim.x + threadIdx.x;
  if (i < NN) g_cnt[i] = 1;  // self loop
}

__global__ void k_hist(const int* __restrict__ ei) {
  int e = blockIdx.x * blockDim.x + threadIdx.x;
  if (e < EE) {
    int d = ei[EE + e];
    atomicAdd(&g_cnt[d], 1);
  }
}

// single-block exclusive scan of g_cnt -> g_off
__global__ void k_scan() {
  __shared__ int sm[1024];
  __shared__ int carry;
  int tid = threadIdx.x;
  if (tid == 0) carry = 0;
  __syncthreads();
  for (int base = 0; base < NN; base += 1024) {
    int i = base + tid;
    int v = (i < NN) ? g_cnt[i] : 0;
    int x = v;
    sm[tid] = x;
    __syncthreads();
#pragma unroll
    for (int o = 1; o < 1024; o <<= 1) {
      int y = (tid >= o) ? sm[tid - o] : 0;
      __syncthreads();
      x += y;
      sm[tid] = x;
      __syncthreads();
    }
    int bc = carry;
    if (i < NN) g_off[i] = bc + x - v;
    __syncthreads();
    if (tid == 1023) carry = bc + x;
    __syncthreads();
  }
  if (tid == 0) g_off[NN] = carry;
}

__global__ void k_self() {
  int i = blockIdx.x * blockDim.x + threadIdx.x;
  if (i < NN) {
    int o = g_off[i];
    g_psrc[o] = i;      // self loop occupies first slot
    g_cur[i] = o + 1;
  }
}

__global__ void k_scatter(const int* __restrict__ ei) {
  int e = blockIdx.x * blockDim.x + threadIdx.x;
  if (e < EE) {
    int s = ei[e];
    int d = ei[EE + e];
    int slot = atomicAdd(&g_cur[d], 1);
    g_psrc[slot] = s;
  }
}

// ---------------- SGEMM: C[M,NC] = A[M,K] * B[K,NC], row-major ---------------
#define BM 64
#define BN 64
#define BK 16

template <int K, int NC>
__device__ __forceinline__ void sgemm_body(const float* __restrict__ A,
                                           const float* __restrict__ B,
                                           float* __restrict__ C, int M) {
  __shared__ float As[BK][BM];
  __shared__ float Bs[BK][BN];
  const int t = threadIdx.x;
  const int bm = blockIdx.x * BM;
  const int bn = blockIdx.y * BN;
  const int tx = t & 15, ty = t >> 4;
  const int arow = t >> 2, acol = (t & 3) << 2;
  const int brow = t >> 4, bcol = (t & 15) << 2;
  float acc[4][4] = {};
  for (int k0 = 0; k0 < K; k0 += BK) {
    int gr = bm + arow;
    float4 av = make_float4(0.f, 0.f, 0.f, 0.f);
    if (gr < M) av = *(const float4*)(A + (size_t)gr * K + k0 + acol);
    As[acol + 0][arow] = av.x;
    As[acol + 1][arow] = av.y;
    As[acol + 2][arow] = av.z;
    As[acol + 3][arow] = av.w;
    float4 bv = *(const float4*)(B + (size_t)(k0 + brow) * NC + bn + bcol);
    *(float4*)&Bs[brow][bcol] = bv;
    __syncthreads();
#pragma unroll
    for (int k = 0; k < BK; k++) {
      float4 a4 = *(const float4*)&As[k][ty << 2];
      float4 b4 = *(const float4*)&Bs[k][tx << 2];
      float a[4] = {a4.x, a4.y, a4.z, a4.w};
      float b[4] = {b4.x, b4.y, b4.z, b4.w};
#pragma unroll
      for (int i = 0; i < 4; i++)
#pragma unroll
        for (int j = 0; j < 4; j++) acc[i][j] += a[i] * b[j];
    }
    __syncthreads();
  }
#pragma unroll
  for (int i = 0; i < 4; i++) {
    int r = bm + (ty << 2) + i;
    if (r < M) {
      float4 v = make_float4(acc[i][0], acc[i][1], acc[i][2], acc[i][3]);
      *(float4*)(C + (size_t)r * NC + bn + (tx << 2)) = v;
    }
  }
}

__global__ __launch_bounds__(256) void k_gemm1(const float* __restrict__ A,
                                               const float* __restrict__ B) {
  sgemm_body<128, C1>(A, B, g_h1, NN);
}
__global__ __launch_bounds__(256) void k_gemm2(const float* __restrict__ B) {
  sgemm_body<C1, C2>(g_h2, B, g_h2lin, NN);
}

// ---------------- attention logits -------------------------------------------
// layer1: warp per node; lane covers 8 contiguous channels (all in one head)
__global__ __launch_bounds__(256) void k_al1(const float* __restrict__ a_src,
                                             const float* __restrict__ a_dst) {
  int w = (blockIdx.x * 256 + threadIdx.x) >> 5;
  int lane = threadIdx.x & 31;
  if (w >= NN) return;
  const float4* hp = (const float4*)(g_h1 + (size_t)w * C1 + (lane << 3));
  float4 h0 = hp[0], h1 = hp[1];
  const float4* sp = (const float4*)(a_src + (lane << 3));
  const float4* dp = (const float4*)(a_dst + (lane << 3));
  float4 s0 = __ldg(sp), s1 = __ldg(sp + 1);
  float4 d0 = __ldg(dp), d1 = __ldg(dp + 1);
  float ss = h0.x * s0.x + h0.y * s0.y + h0.z * s0.z + h0.w * s0.w +
             h1.x * s1.x + h1.y * s1.y + h1.z * s1.z + h1.w * s1.w;
  float dd = h0.x * d0.x + h0.y * d0.y + h0.z * d0.z + h0.w * d0.w +
             h1.x * d1.x + h1.y * d1.y + h1.z * d1.z + h1.w * d1.w;
#pragma unroll
  for (int o = 1; o < 8; o <<= 1) {
    ss += __shfl_xor_sync(0xffffffffu, ss, o);
    dd += __shfl_xor_sync(0xffffffffu, dd, o);
  }
  if ((lane & 7) == 0) {
    int hd = lane >> 3;
    g_als1[w * 4 + hd] = ss;
    g_ald1[w * 4 + hd] = dd;
  }
}

__global__ __launch_bounds__(256) void k_al2(const float* __restrict__ a_src,
                                             const float* __restrict__ a_dst) {
  int w = (blockIdx.x * 256 + threadIdx.x) >> 5;
  int lane = threadIdx.x & 31;
  if (w >= NN) return;
  int c = lane << 1;
  float2 h = *(const float2*)(g_h2lin + (size_t)w * C2 + c);
  float ss = h.x * __ldg(a_src + c) + h.y * __ldg(a_src + c + 1);
  float dd = h.x * __ldg(a_dst + c) + h.y * __ldg(a_dst + c + 1);
#pragma unroll
  for (int o = 16; o; o >>= 1) {
    ss += __shfl_xor_sync(0xffffffffu, ss, o);
    dd += __shfl_xor_sync(0xffffffffu, dd, o);
  }
  if (lane == 0) {
    g_als2[w] = ss;
    g_ald2[w] = dd;
  }
}

// ---------------- layer1 aggregation: warp per dst node ----------------------
__global__ __launch_bounds__(256) void k_agg1(const float* __restrict__ b1) {
  int w = (blockIdx.x * 256 + threadIdx.x) >> 5;
  int lane = threadIdx.x & 31;
  if (w >= NN) return;
  const int node = w;
  const int off = g_off[node], end = g_off[node + 1];
  float4 ad = *(const float4*)&g_ald1[node * 4];

  float m0 = -3e38f, m1 = -3e38f, m2 = -3e38f, m3 = -3e38f;
  for (int j = off + lane; j < end; j += 32) {
    int s = g_psrc[j];
    float4 as = __ldg((const float4*)&g_als1[s * 4]);
    m0 = fmaxf(m0, lrelu(as.x + ad.x));
    m1 = fmaxf(m1, lrelu(as.y + ad.y));
    m2 = fmaxf(m2, lrelu(as.z + ad.z));
    m3 = fmaxf(m3, lrelu(as.w + ad.w));
  }
#pragma unroll
  for (int o = 16; o; o >>= 1) {
    m0 = fmaxf(m0, __shfl_xor_sync(0xffffffffu, m0, o));
    m1 = fmaxf(m1, __shfl_xor_sync(0xffffffffu, m1, o));
    m2 = fmaxf(m2, __shfl_xor_sync(0xffffffffu, m2, o));
    m3 = fmaxf(m3, __shfl_xor_sync(0xffffffffu, m3, o));
  }
  float s0 = 0.f, s1 = 0.f, s2 = 0.f, s3 = 0.f;
  for (int j = off + lane; j < end; j += 32) {
    int s = g_psrc[j];
    float4 as = __ldg((const float4*)&g_als1[s * 4]);
    s0 += __expf(lrelu(as.x + ad.x) - m0);
    s1 += __expf(lrelu(as.y + ad.y) - m1);
    s2 += __expf(lrelu(as.z + ad.z) - m2);
    s3 += __expf(lrelu(as.w + ad.w) - m3);
  }
#pragma unroll
  for (int o = 16; o; o >>= 1) {
    s0 += __shfl_xor_sync(0xffffffffu, s0, o);
    s1 += __shfl_xor_sync(0xffffffffu, s1, o);
    s2 += __shfl_xor_sync(0xffffffffu, s2, o);
    s3 += __shfl_xor_sync(0xffffffffu, s3, o);
  }
  const int hd = lane >> 3;
  float mh = hd == 0 ? m0 : hd == 1 ? m1 : hd == 2 ? m2 : m3;
  float sh = hd == 0 ? s0 : hd == 1 ? s1 : hd == 2 ? s2 : s3;
  float adh = hd == 0 ? ad.x : hd == 1 ? ad.y : hd == 2 ? ad.z : ad.w;
  float inv = 1.f / (sh + 1e-16f);

  float acc[8] = {0.f, 0.f, 0.f, 0.f, 0.f, 0.f, 0.f, 0.f};
  const int myc = lane << 3;
  for (int j = off; j < end; j++) {
    int s = g_psrc[j];
    float asv = __ldg(&g_als1[s * 4 + hd]);
    float alpha = __expf(lrelu(asv + adh) - mh) * inv;
    const float4* hp = (const float4*)(g_h1 + (size_t)s * C1 + myc);
    float4 p = __ldg(hp), q = __ldg(hp + 1);
    acc[0] += p.x * alpha; acc[1] += p.y * alpha;
    acc[2] += p.z * alpha; acc[3] += p.w * alpha;
    acc[4] += q.x * alpha; acc[5] += q.y * alpha;
    acc[6] += q.z * alpha; acc[7] += q.w * alpha;
  }
  float4 bb0 = __ldg((const float4*)&b1[myc]);
  float4 bb1 = __ldg((const float4*)&b1[myc + 4]);
  float4 o0, o1;
  o0.x = elu_f(acc[0] + bb0.x); o0.y = elu_f(acc[1] + bb0.y);
  o0.z = elu_f(acc[2] + bb0.z); o0.w = elu_f(acc[3] + bb0.w);
  o1.x = elu_f(acc[4] + bb1.x); o1.y = elu_f(acc[5] + bb1.y);
  o1.z = elu_f(acc[6] + bb1.z); o1.w = elu_f(acc[7] + bb1.w);
  *(float4*)(g_h2 + (size_t)node * C1 + myc) = o0;
  *(float4*)(g_h2 + (size_t)node * C1 + myc + 4) = o1;
}

// ---------------- layer2 aggregation: warp per dst node ----------------------
__global__ __launch_bounds__(256) void k_agg2(const float* __restrict__ b2,
                                              float* __restrict__ out) {
  int w = (blockIdx.x * 256 + threadIdx.x) >> 5;
  int lane = threadIdx.x & 31;
  if (w >= NN) return;
  const int node = w;
  const int off = g_off[node], end = g_off[node + 1];
  float ad = g_ald2[node];

  float m = -3e38f;
  for (int j = off + lane; j < end; j += 32) {
    int s = g_psrc[j];
    m = fmaxf(m, lrelu(__ldg(&g_als2[s]) + ad));
  }
#pragma unroll
  for (int o = 16; o; o >>= 1) m = fmaxf(m, __shfl_xor_sync(0xffffffffu, m, o));
  float su = 0.f;
  for (int j = off + lane; j < end; j += 32) {
    int s = g_psrc[j];
    su += __expf(lrelu(__ldg(&g_als2[s]) + ad) - m);
  }
#pragma unroll
  for (int o = 16; o; o >>= 1) su += __shfl_xor_sync(0xffffffffu, su, o);
  float inv = 1.f / (su + 1e-16f);

  float a0 = 0.f, a1 = 0.f;
  const int c = lane << 1;
  for (int j = off; j < end; j++) {
    int s = g_psrc[j];
    float alpha = __expf(lrelu(__ldg(&g_als2[s]) + ad) - m) * inv;
    float2 p = __ldg((const float2*)(g_h2lin + (size_t)s * C2 + c));
    a0 += p.x * alpha;
    a1 += p.y * alpha;
  }
  float2 r;
  r.x = elu_f(a0 + __ldg(&b2[c]));
  r.y = elu_f(a1 + __ldg(&b2[c + 1]));
  *(float2*)(out + (size_t)node * C2 + c) = r;
}

// ---------------- launch ------------------------------------------------------
extern "C" void kernel_launch(void* const* d_in, const int* in_sizes, int n_in,
                              void* d_out, int out_size) {
  const float* x = (const float*)d_in[0];
  const int* ei = (const int*)d_in[1];
  const float* W1 = (const float*)d_in[2];
  const float* as1 = (const float*)d_in[3];
  const float* ad1 = (const float*)d_in[4];
  const float* b1 = (const float*)d_in[5];
  const float* W2 = (const float*)d_in[6];
  const float* as2 = (const float*)d_in[7];
  const float* ad2 = (const float*)d_in[8];
  const float* b2 = (const float*)d_in[9];
  float* out = (float*)d_out;

  // CSR build (by dst, self loop in first slot)
  k_init<<<(NN + 255) / 256, 256>>>();
  k_hist<<<(EE + 255) / 256, 256>>>(ei);
  k_scan<<<1, 1024>>>();
  k_self<<<(NN + 255) / 256, 256>>>();
  k_scatter<<<(EE + 255) / 256, 256>>>(ei);

  // layer 1
  dim3 g1((NN + BM - 1) / BM, C1 / BN);
  k_gemm1<<<g1, 256>>>(x, W1);
  int nwb = (NN * 32 + 255) / 256;  // blocks of 8 warps, warp per node
  k_al1<<<nwb, 256>>>(as1, ad1);
  k_agg1<<<nwb, 256>>>(b1);

  // layer 2
  dim3 g2((NN + BM - 1) / BM, C2 / BN);
  k_gemm2<<<g2, 256>>>(W2);
  k_al2<<<nwb, 256>>>(as2, ad2);
  k_agg2<<<nwb, 256>>>(b2, out);
}

// round 4
// speedup vs baseline: 1.2344x; 1.2344x over previous
#include <cuda_runtime.h>

#define NN 50000
#define EE 800000
#define ET (EE + NN)
#define HEADS 4
#define HID 64
#define C1 256   /* HEADS*HID */
#define C2 64
#define NEG 0.2f

// ---------------- scratch (device globals; no cudaMalloc allowed) -------------
__device__ __align__(16) float g_h1[(size_t)NN * C1];     // x@W1
__device__ __align__(16) float g_als1[NN * HEADS];
__device__ __align__(16) float g_ald1[NN * HEADS];
__device__ __align__(16) float g_h2[(size_t)NN * C1];     // elu(agg1 + b1)
__device__ __align__(16) float g_h2lin[(size_t)NN * C2];  // h2@W2
__device__ float g_als2[NN];
__device__ float g_ald2[NN];
__device__ int   g_cnt[NN];
__device__ int   g_off[NN + 1];
__device__ int   g_cur[NN];
__device__ int   g_psrc[ET];
__device__ int   g_bsum[256];

__device__ __forceinline__ float lrelu(float x) { return x > 0.f ? x : NEG * x; }
__device__ __forceinline__ float elu_f(float x) { return x > 0.f ? x : __expf(x) - 1.f; }

// ---------------- CSR build ---------------------------------------------------
__global__ void k_init() {
  int i = blockIdx.x * blockDim.x + threadIdx.x;
  if (i < NN) g_cnt[i] = 1;  // self loop
}

__global__ void k_hist(const int* __restrict__ ei) {
  int e = blockIdx.x * blockDim.x + threadIdx.x;
  if (e < EE) {
    int d = ei[EE + e];
    atomicAdd(&g_cnt[d], 1);
  }
}

// stage 1: per-block (256-wide) exclusive scan, block totals to g_bsum
__global__ __launch_bounds__(256) void k_scan1() {
  int i = blockIdx.x * 256 + threadIdx.x;
  int v = (i < NN) ? g_cnt[i] : 0;
  int lane = threadIdx.x & 31, wid = threadIdx.x >> 5;
  int x = v;
#pragma unroll
  for (int o = 1; o < 32; o <<= 1) {
    int y = __shfl_up_sync(0xffffffffu, x, o);
    if (lane >= o) x += y;
  }
  __shared__ int ws[8];
  if (lane == 31) ws[wid] = x;
  __syncthreads();
  if (threadIdx.x < 8) {
    int z = ws[threadIdx.x];
#pragma unroll
    for (int o = 1; o < 8; o <<= 1) {
      int q = __shfl_up_sync(0xffu, z, o);
      if ((int)threadIdx.x >= o) z += q;
    }
    ws[threadIdx.x] = z;
  }
  __syncthreads();
  int incl = x + (wid ? ws[wid - 1] : 0);
  if (i < NN) g_off[i] = incl - v;
  if (threadIdx.x == 255) g_bsum[blockIdx.x] = incl;
}

// stage 2: single block scans the 196 block sums (exclusive, in place)
__global__ __launch_bounds__(256) void k_scan2() {
  const int NB = (NN + 255) / 256;
  int t = threadIdx.x;
  int v = (t < NB) ? g_bsum[t] : 0;
  int lane = t & 31, wid = t >> 5;
  int x = v;
#pragma unroll
  for (int o = 1; o < 32; o <<= 1) {
    int y = __shfl_up_sync(0xffffffffu, x, o);
    if (lane >= o) x += y;
  }
  __shared__ int ws[8];
  if (lane == 31) ws[wid] = x;
  __syncthreads();
  if (t < 8) {
    int z = ws[t];
#pragma unroll
    for (int o = 1; o < 8; o <<= 1) {
      int q = __shfl_up_sync(0xffu, z, o);
      if (t >= o) z += q;
    }
    ws[t] = z;
  }
  __syncthreads();
  int incl = x + (wid ? ws[wid - 1] : 0);
  if (t < NB) g_bsum[t] = incl - v;
}

// stage 3: add block offsets; also place self loop + init cursor (fused k_self)
__global__ void k_scan3() {
  int i = blockIdx.x * blockDim.x + threadIdx.x;
  if (i < NN) {
    int o = g_off[i] + g_bsum[i >> 8];
    g_off[i] = o;
    g_psrc[o] = i;   // self loop occupies first slot
    g_cur[i] = o + 1;
  }
  if (i == 0) g_off[NN] = ET;
}

__global__ void k_scatter(const int* __restrict__ ei) {
  int e = blockIdx.x * blockDim.x + threadIdx.x;
  if (e < EE) {
    int s = ei[e];
    int d = ei[EE + e];
    int slot = atomicAdd(&g_cur[d], 1);
    g_psrc[slot] = s;
  }
}

// ---------------- SGEMM (device-global outputs bound inside kernel) ----------
// MODE 1: g_h1[NN,256] = A_in[NN,128] @ B[128,256]
// MODE 2: g_h2lin[NN,64] = g_h2[NN,256] @ B[256,64]
template <int MODE>
__global__ __launch_bounds__(256) void k_sgemm(const float* __restrict__ A_in,
                                               const float* __restrict__ B) {
  constexpr int K  = (MODE == 1) ? 128 : C1;
  constexpr int NC = (MODE == 1) ? C1 : C2;
  constexpr int BN = (MODE == 1) ? 128 : 64;
  constexpr int TN = (MODE == 1) ? 8 : 4;
  constexpr int M  = NN;
  constexpr int BM = 128, BK = 16, BMP = BM + 4;
  constexpr int BN4 = BN / 4;
  constexpr int BLOADS = (BK * BN4) / 256;  // 2 for BN=128, 1 for BN=64

  const float* A = (MODE == 1) ? A_in : (const float*)g_h2;
  float* C = (MODE == 1) ? g_h1 : g_h2lin;

  __shared__ float As[2][BK][BMP];
  __shared__ float Bs[2][BK][BN];
  const int t = threadIdx.x;
  const int bm = blockIdx.x * BM;
  const int bn = blockIdx.y * BN;
  const int tx = t & 15, ty = t >> 4;
  const int ar0 = t >> 2;            // 0..63 (plus +64 twin)
  const int ac0 = (t & 3) << 2;      // 0,4,8,12
  const int br0 = t / BN4;
  const int bc0 = (t % BN4) << 2;

  float4 apre0, apre1, bpre0, bpre1;

  // prologue: load tile 0
  {
    int gr0 = bm + ar0, gr1 = gr0 + 64;
    apre0 = (gr0 < M) ? *(const float4*)(A + (size_t)gr0 * K + ac0)
                      : make_float4(0.f, 0.f, 0.f, 0.f);
    apre1 = (gr1 < M) ? *(const float4*)(A + (size_t)gr1 * K + ac0)
                      : make_float4(0.f, 0.f, 0.f, 0.f);
    bpre0 = *(const float4*)(B + (size_t)br0 * NC + bn + bc0);
    if constexpr (BLOADS == 2)
      bpre1 = *(const float4*)(B + (size_t)(br0 + 8) * NC + bn + bc0);
  }
  {
    As[0][ac0 + 0][ar0] = apre0.x; As[0][ac0 + 1][ar0] = apre0.y;
    As[0][ac0 + 2][ar0] = apre0.z; As[0][ac0 + 3][ar0] = apre0.w;
    As[0][ac0 + 0][ar0 + 64] = apre1.x; As[0][ac0 + 1][ar0 + 64] = apre1.y;
    As[0][ac0 + 2][ar0 + 64] = apre1.z; As[0][ac0 + 3][ar0 + 64] = apre1.w;
    *(float4*)&Bs[0][br0][bc0] = bpre0;
    if constexpr (BLOADS == 2) *(float4*)&Bs[0][br0 + 8][bc0] = bpre1;
  }
  __syncthreads();

  float acc[8][TN] = {};
  int buf = 0;
#pragma unroll 1
  for (int k0 = BK; k0 <= K; k0 += BK) {
    if (k0 < K) {
      int gr0 = bm + ar0, gr1 = gr0 + 64;
      apre0 = (gr0 < M) ? *(const float4*)(A + (size_t)gr0 * K + k0 + ac0)
                        : make_float4(0.f, 0.f, 0.f, 0.f);
      apre1 = (gr1 < M) ? *(const float4*)(A + (size_t)gr1 * K + k0 + ac0)
                        : make_float4(0.f, 0.f, 0.f, 0.f);
      bpre0 = *(const float4*)(B + (size_t)(k0 + br0) * NC + bn + bc0);
      if constexpr (BLOADS == 2)
        bpre1 = *(const float4*)(B + (size_t)(k0 + br0 + 8) * NC + bn + bc0);
    }
#pragma unroll
    for (int k = 0; k < BK; k++) {
      float4 a0 = *(const float4*)&As[buf][k][ty << 3];
      float4 a1 = *(const float4*)&As[buf][k][(ty << 3) + 4];
      float a[8] = {a0.x, a0.y, a0.z, a0.w, a1.x, a1.y, a1.z, a1.w};
      float b[TN];
#pragma unroll
      for (int j = 0; j < TN; j += 4) {
        float4 b4 = *(const float4*)&Bs[buf][k][tx * TN + j];
        b[j] = b4.x; b[j + 1] = b4.y; b[j + 2] = b4.z; b[j + 3] = b4.w;
      }
#pragma unroll
      for (int i = 0; i < 8; i++)
#pragma unroll
        for (int j = 0; j < TN; j++) acc[i][j] += a[i] * b[j];
    }
    if (k0 < K) {
      int nb = buf ^ 1;
      As[nb][ac0 + 0][ar0] = apre0.x; As[nb][ac0 + 1][ar0] = apre0.y;
      As[nb][ac0 + 2][ar0] = apre0.z; As[nb][ac0 + 3][ar0] = apre0.w;
      As[nb][ac0 + 0][ar0 + 64] = apre1.x; As[nb][ac0 + 1][ar0 + 64] = apre1.y;
      As[nb][ac0 + 2][ar0 + 64] = apre1.z; As[nb][ac0 + 3][ar0 + 64] = apre1.w;
      *(float4*)&Bs[nb][br0][bc0] = bpre0;
      if constexpr (BLOADS == 2) *(float4*)&Bs[nb][br0 + 8][bc0] = bpre1;
      __syncthreads();
      buf = nb;
    }
  }

#pragma unroll
  for (int i = 0; i < 8; i++) {
    int r = bm + (ty << 3) + i;
    if (r < M) {
#pragma unroll
      for (int j = 0; j < TN; j += 4) {
        float4 v = make_float4(acc[i][j], acc[i][j + 1], acc[i][j + 2], acc[i][j + 3]);
        *(float4*)(C + (size_t)r * NC + bn + tx * TN + j) = v;
      }
    }
  }
}

// ---------------- attention logits -------------------------------------------
__global__ __launch_bounds__(256) void k_al1(const float* __restrict__ a_src,
                                             const float* __restrict__ a_dst) {
  int w = (blockIdx.x * 256 + threadIdx.x) >> 5;
  int lane = threadIdx.x & 31;
  if (w >= NN) return;
  const float4* hp = (const float4*)(g_h1 + (size_t)w * C1 + (lane << 3));
  float4 h0 = hp[0], h1 = hp[1];
  const float4* sp = (const float4*)(a_src + (lane << 3));
  const float4* dp = (const float4*)(a_dst + (lane << 3));
  float4 s0 = __ldg(sp), s1 = __ldg(sp + 1);
  float4 d0 = __ldg(dp), d1 = __ldg(dp + 1);
  float ss = h0.x * s0.x + h0.y * s0.y + h0.z * s0.z + h0.w * s0.w +
             h1.x * s1.x + h1.y * s1.y + h1.z * s1.z + h1.w * s1.w;
  float dd = h0.x * d0.x + h0.y * d0.y + h0.z * d0.z + h0.w * d0.w +
             h1.x * d1.x + h1.y * d1.y + h1.z * d1.z + h1.w * d1.w;
#pragma unroll
  for (int o = 1; o < 8; o <<= 1) {
    ss += __shfl_xor_sync(0xffffffffu, ss, o);
    dd += __shfl_xor_sync(0xffffffffu, dd, o);
  }
  if ((lane & 7) == 0) {
    int hd = lane >> 3;
    g_als1[w * 4 + hd] = ss;
    g_ald1[w * 4 + hd] = dd;
  }
}

__global__ __launch_bounds__(256) void k_al2(const float* __restrict__ a_src,
                                             const float* __restrict__ a_dst) {
  int w = (blockIdx.x * 256 + threadIdx.x) >> 5;
  int lane = threadIdx.x & 31;
  if (w >= NN) return;
  int c = lane << 1;
  float2 h = *(const float2*)(g_h2lin + (size_t)w * C2 + c);
  float ss = h.x * __ldg(a_src + c) + h.y * __ldg(a_src + c + 1);
  float dd = h.x * __ldg(a_dst + c) + h.y * __ldg(a_dst + c + 1);
#pragma unroll
  for (int o = 16; o; o >>= 1) {
    ss += __shfl_xor_sync(0xffffffffu, ss, o);
    dd += __shfl_xor_sync(0xffffffffu, dd, o);
  }
  if (lane == 0) {
    g_als2[w] = ss;
    g_ald2[w] = dd;
  }
}

// ---------------- layer1 aggregation: warp per dst node ----------------------
__global__ __launch_bounds__(256) void k_agg1(const float* __restrict__ b1) {
  int w = (blockIdx.x * 256 + threadIdx.x) >> 5;
  int lane = threadIdx.x & 31;
  if (w >= NN) return;
  const int node = w;
  const int off = g_off[node], end = g_off[node + 1];
  float4 ad = *(const float4*)&g_ald1[node * 4];

  float m0 = -3e38f, m1 = -3e38f, m2 = -3e38f, m3 = -3e38f;
  for (int j = off + lane; j < end; j += 32) {
    int s = g_psrc[j];
    float4 as = __ldg((const float4*)&g_als1[s * 4]);
    m0 = fmaxf(m0, lrelu(as.x + ad.x));
    m1 = fmaxf(m1, lrelu(as.y + ad.y));
    m2 = fmaxf(m2, lrelu(as.z + ad.z));
    m3 = fmaxf(m3, lrelu(as.w + ad.w));
  }
#pragma unroll
  for (int o = 16; o; o >>= 1) {
    m0 = fmaxf(m0, __shfl_xor_sync(0xffffffffu, m0, o));
    m1 = fmaxf(m1, __shfl_xor_sync(0xffffffffu, m1, o));
    m2 = fmaxf(m2, __shfl_xor_sync(0xffffffffu, m2, o));
    m3 = fmaxf(m3, __shfl_xor_sync(0xffffffffu, m3, o));
  }
  float s0 = 0.f, s1 = 0.f, s2 = 0.f, s3 = 0.f;
  for (int j = off + lane; j < end; j += 32) {
    int s = g_psrc[j];
    float4 as = __ldg((const float4*)&g_als1[s * 4]);
    s0 += __expf(lrelu(as.x + ad.x) - m0);
    s1 += __expf(lrelu(as.y + ad.y) - m1);
    s2 += __expf(lrelu(as.z + ad.z) - m2);
    s3 += __expf(lrelu(as.w + ad.w) - m3);
  }
#pragma unroll
  for (int o = 16; o; o >>= 1) {
    s0 += __shfl_xor_sync(0xffffffffu, s0, o);
    s1 += __shfl_xor_sync(0xffffffffu, s1, o);
    s2 += __shfl_xor_sync(0xffffffffu, s2, o);
    s3 += __shfl_xor_sync(0xffffffffu, s3, o);
  }
  const int hd = lane >> 3;
  float mh = hd == 0 ? m0 : hd == 1 ? m1 : hd == 2 ? m2 : m3;
  float sh = hd == 0 ? s0 : hd == 1 ? s1 : hd == 2 ? s2 : s3;
  float adh = hd == 0 ? ad.x : hd == 1 ? ad.y : hd == 2 ? ad.z : ad.w;
  float inv = 1.f / (sh + 1e-16f);

  float acc[8] = {0.f, 0.f, 0.f, 0.f, 0.f, 0.f, 0.f, 0.f};
  const int myc = lane << 3;
  for (int j = off; j < end; j++) {
    int s = g_psrc[j];
    float asv = __ldg(&g_als1[s * 4 + hd]);
    float alpha = __expf(lrelu(asv + adh) - mh) * inv;
    const float4* hp = (const float4*)(g_h1 + (size_t)s * C1 + myc);
    float4 p = __ldg(hp), q = __ldg(hp + 1);
    acc[0] += p.x * alpha; acc[1] += p.y * alpha;
    acc[2] += p.z * alpha; acc[3] += p.w * alpha;
    acc[4] += q.x * alpha; acc[5] += q.y * alpha;
    acc[6] += q.z * alpha; acc[7] += q.w * alpha;
  }
  float4 bb0 = __ldg((const float4*)&b1[myc]);
  float4 bb1 = __ldg((const float4*)&b1[myc + 4]);
  float4 o0, o1;
  o0.x = elu_f(acc[0] + bb0.x); o0.y = elu_f(acc[1] + bb0.y);
  o0.z = elu_f(acc[2] + bb0.z); o0.w = elu_f(acc[3] + bb0.w);
  o1.x = elu_f(acc[4] + bb1.x); o1.y = elu_f(acc[5] + bb1.y);
  o1.z = elu_f(acc[6] + bb1.z); o1.w = elu_f(acc[7] + bb1.w);
  *(float4*)(g_h2 + (size_t)node * C1 + myc) = o0;
  *(float4*)(g_h2 + (size_t)node * C1 + myc + 4) = o1;
}

// ---------------- layer2 aggregation: warp per dst node ----------------------
__global__ __launch_bounds__(256) void k_agg2(const float* __restrict__ b2,
                                              float* __restrict__ out) {
  int w = (blockIdx.x * 256 + threadIdx.x) >> 5;
  int lane = threadIdx.x & 31;
  if (w >= NN) return;
  const int node = w;
  const int off = g_off[node], end = g_off[node + 1];
  float ad = g_ald2[node];

  float m = -3e38f;
  for (int j = off + lane; j < end; j += 32) {
    int s = g_psrc[j];
    m = fmaxf(m, lrelu(__ldg(&g_als2[s]) + ad));
  }
#pragma unroll
  for (int o = 16; o; o >>= 1) m = fmaxf(m, __shfl_xor_sync(0xffffffffu, m, o));
  float su = 0.f;
  for (int j = off + lane; j < end; j += 32) {
    int s = g_psrc[j];
    su += __expf(lrelu(__ldg(&g_als2[s]) + ad) - m);
  }
#pragma unroll
  for (int o = 16; o; o >>= 1) su += __shfl_xor_sync(0xffffffffu, su, o);
  float inv = 1.f / (su + 1e-16f);

  float a0 = 0.f, a1 = 0.f;
  const int c = lane << 1;
  for (int j = off; j < end; j++) {
    int s = g_psrc[j];
    float alpha = __expf(lrelu(__ldg(&g_als2[s]) + ad) - m) * inv;
    float2 p = __ldg((const float2*)(g_h2lin + (size_t)s * C2 + c));
    a0 += p.x * alpha;
    a1 += p.y * alpha;
  }
  float2 r;
  r.x = elu_f(a0 + __ldg(&b2[c]));
  r.y = elu_f(a1 + __ldg(&b2[c + 1]));
  *(float2*)(out + (size_t)node * C2 + c) = r;
}

// ---------------- launch ------------------------------------------------------
extern "C" void kernel_launch(void* const* d_in, const int* in_sizes, int n_in,
                              void* d_out, int out_size) {
  const float* x = (const float*)d_in[0];
  const int* ei = (const int*)d_in[1];
  const float* W1 = (const float*)d_in[2];
  const float* as1 = (const float*)d_in[3];
  const float* ad1 = (const float*)d_in[4];
  const float* b1 = (const float*)d_in[5];
  const float* W2 = (const float*)d_in[6];
  const float* as2 = (const float*)d_in[7];
  const float* ad2 = (const float*)d_in[8];
  const float* b2 = (const float*)d_in[9];
  float* out = (float*)d_out;

  const int NB = (NN + 255) / 256;  // 196

  // CSR build (by dst, self loop in first slot)
  k_init<<<NB, 256>>>();
  k_hist<<<(EE + 255) / 256, 256>>>(ei);
  k_scan1<<<NB, 256>>>();
  k_scan2<<<1, 256>>>();
  k_scan3<<<NB, 256>>>();
  k_scatter<<<(EE + 255) / 256, 256>>>(ei);

  // layer 1
  dim3 g1((NN + 127) / 128, C1 / 128);
  k_sgemm<1><<<g1, 256>>>(x, W1);
  int nwb = (NN * 32 + 255) / 256;  // warp per node
  k_al1<<<nwb, 256>>>(as1, ad1);
  k_agg1<<<nwb, 256>>>(b1);

  // layer 2
  dim3 g2((NN + 127) / 128, C2 / 64);
  k_sgemm<2><<<g2, 256>>>(nullptr, W2);
  k_al2<<<nwb, 256>>>(as2, ad2);
  k_agg2<<<nwb, 256>>>(b2, out);
}

// round 6
// speedup vs baseline: 1.4313x; 1.1595x over previous
#include <cuda_runtime.h>
#include <cuda_bf16.h>
#include <mma.h>
#include <cstdint>

using namespace nvcuda;

#define NN 50000
#define EE 800000
#define ET (EE + NN)
#define HEADS 4
#define HID 64
#define C1 256   /* HEADS*HID */
#define C2 64
#define NEG 0.2f

// ---------------- scratch (device globals; no cudaMalloc allowed) -------------
__device__ __align__(16) float g_h1[(size_t)NN * C1];     // layer1 features fp32
__device__ __align__(16) float g_als1[NN * HEADS];
__device__ __align__(16) float g_ald1[NN * HEADS];
__device__ __align__(16) float g_h2lin[(size_t)NN * C2];
__device__ float g_als2[NN];
__device__ float g_ald2[NN];
__device__ int   g_cnt[NN];
__device__ int   g_off[NN + 1];
__device__ int   g_cur[NN];
__device__ int   g_psrc[ET];
__device__ int   g_bsum[256];
// bf16 hi/lo operands for tensor-core GEMMs (same layout as fp32 originals)
__device__ __align__(16) __nv_bfloat16 g_xhi[(size_t)NN * 128];
__device__ __align__(16) __nv_bfloat16 g_xlo[(size_t)NN * 128];
__device__ __align__(16) __nv_bfloat16 g_h2hi[(size_t)NN * C1];
__device__ __align__(16) __nv_bfloat16 g_h2lo[(size_t)NN * C1];
__device__ __align__(16) __nv_bfloat16 g_w1hi[128 * C1];   // [k=128][n=256]
__device__ __align__(16) __nv_bfloat16 g_w1lo[128 * C1];
__device__ __align__(16) __nv_bfloat16 g_w2hi[C1 * C2];    // [k=256][n=64]
__device__ __align__(16) __nv_bfloat16 g_w2lo[C1 * C2];

__device__ __forceinline__ float lrelu(float x) { return x > 0.f ? x : NEG * x; }
__device__ __forceinline__ float elu_f(float x) { return x > 0.f ? x : __expf(x) - 1.f; }

// ---------------- CSR build ---------------------------------------------------
__global__ void k_hist(const int* __restrict__ ei) {
  int e = blockIdx.x * blockDim.x + threadIdx.x;
  if (e < EE) atomicAdd(&g_cnt[ei[EE + e]], 1);
}

// per-block exclusive scan; +1 self loop folded in; resets g_cnt for next replay
__global__ __launch_bounds__(256) void k_scan1() {
  int i = blockIdx.x * 256 + threadIdx.x;
  int v = 0;
  if (i < NN) { v = g_cnt[i] + 1; g_cnt[i] = 0; }
  int lane = threadIdx.x & 31, wid = threadIdx.x >> 5;
  int x = v;
#pragma unroll
  for (int o = 1; o < 32; o <<= 1) {
    int y = __shfl_up_sync(0xffffffffu, x, o);
    if (lane >= o) x += y;
  }
  __shared__ int ws[8];
  if (lane == 31) ws[wid] = x;
  __syncthreads();
  if (threadIdx.x < 8) {
    int z = ws[threadIdx.x];
#pragma unroll
    for (int o = 1; o < 8; o <<= 1) {
      int q = __shfl_up_sync(0xffu, z, o);
      if ((int)threadIdx.x >= o) z += q;
    }
    ws[threadIdx.x] = z;
  }
  __syncthreads();
  int incl = x + (wid ? ws[wid - 1] : 0);
  if (i < NN) g_off[i] = incl - v;
  if (threadIdx.x == 255) g_bsum[blockIdx.x] = incl;
}

__global__ __launch_bounds__(256) void k_scan2() {
  const int NB = (NN + 255) / 256;
  int t = threadIdx.x;
  int v = (t < NB) ? g_bsum[t] : 0;
  int lane = t & 31, wid = t >> 5;
  int x = v;
#pragma unroll
  for (int o = 1; o < 32; o <<= 1) {
    int y = __shfl_up_sync(0xffffffffu, x, o);
    if (lane >= o) x += y;
  }
  __shared__ int ws[8];
  if (lane == 31) ws[wid] = x;
  __syncthreads();
  if (t < 8) {
    int z = ws[t];
#pragma unroll
    for (int o = 1; o < 8; o <<= 1) {
      int q = __shfl_up_sync(0xffu, z, o);
      if (t >= o) z += q;
    }
    ws[t] = z;
  }
  __syncthreads();
  int incl = x + (wid ? ws[wid - 1] : 0);
  if (t < NB) g_bsum[t] = incl - v;
}

__global__ void k_scan3() {
  int i = blockIdx.x * blockDim.x + threadIdx.x;
  if (i < NN) {
    int o = g_off[i] + g_bsum[i >> 8];
    g_off[i] = o;
    g_psrc[o] = i;   // self loop first slot
    g_cur[i] = o + 1;
  }
  if (i == 0) g_off[NN] = ET;
}

__global__ void k_scatter(const int* __restrict__ ei) {
  int e = blockIdx.x * blockDim.x + threadIdx.x;
  if (e < EE) {
    int s = ei[e];
    int d = ei[EE + e];
    g_psrc[atomicAdd(&g_cur[d], 1)] = s;
  }
}

// ---------------- fp32 -> bf16 hi/lo conversions -------------------------------
__global__ void k_cvt_x(const float* __restrict__ x) {
  int i = blockIdx.x * blockDim.x + threadIdx.x;   // float4 index
  const int n4 = NN * 128 / 4;
  if (i >= n4) return;
  float4 v = __ldg((const float4*)x + i);
  float vv[4] = {v.x, v.y, v.z, v.w};
  __nv_bfloat16 h[4], l[4];
#pragma unroll
  for (int q = 0; q < 4; q++) {
    h[q] = __float2bfloat16(vv[q]);
    l[q] = __float2bfloat16(vv[q] - __bfloat162float(h[q]));
  }
  ((__nv_bfloat162*)g_xhi)[2 * i]     = __nv_bfloat162(h[0], h[1]);
  ((__nv_bfloat162*)g_xhi)[2 * i + 1] = __nv_bfloat162(h[2], h[3]);
  ((__nv_bfloat162*)g_xlo)[2 * i]     = __nv_bfloat162(l[0], l[1]);
  ((__nv_bfloat162*)g_xlo)[2 * i + 1] = __nv_bfloat162(l[2], l[3]);
}

__global__ void k_cvt_w(const float* __restrict__ W1,
                        const float* __restrict__ W2) {
  int i = blockIdx.x * blockDim.x + threadIdx.x;
  if (i < 128 * 256) {
    float v = __ldg(&W1[i]);
    __nv_bfloat16 h = __float2bfloat16(v);
    g_w1hi[i] = h;
    g_w1lo[i] = __float2bfloat16(v - __bfloat162float(h));
  }
  if (i < 256 * 64) {
    float v = __ldg(&W2[i]);
    __nv_bfloat16 h = __float2bfloat16(v);
    g_w2hi[i] = h;
    g_w2lo[i] = __float2bfloat16(v - __bfloat162float(h));
  }
}

// ---------------- wmma bf16 split-precision GEMM ------------------------------
// C[NN,NC] = A[NN,K] @ B[K,NC];  D = AhiBhi + AhiBlo + AloBhi (fp32 acc)
// MODE 1: A = g_xhi/lo, B = g_w1hi/lo, C = g_h1   (K=128, NC=256, BN=128)
// MODE 2: A = g_h2hi/lo, B = g_w2hi/lo, C = g_h2lin (K=256, NC=64, BN=64)
template <int MODE>
__global__ __launch_bounds__(256) void k_wgemm() {
  constexpr int K  = (MODE == 1) ? 128 : 256;
  constexpr int NC = (MODE == 1) ? 256 : 64;
  constexpr int BN = (MODE == 1) ? 128 : 64;
  constexpr int BM = 128, BK = 32;
  constexpr int LDA = BK + 8;    // 40 elems (80 B rows, 16B-aligned vec slots)
  constexpr int LDB = BN + 8;
  constexpr int NJ = BN / 32;    // frags per warp in N (4 or 2)

  const __nv_bfloat16* Ahi = (MODE == 1) ? g_xhi : g_h2hi;
  const __nv_bfloat16* Alo = (MODE == 1) ? g_xlo : g_h2lo;
  const __nv_bfloat16* Bhi = (MODE == 1) ? g_w1hi : g_w2hi;
  const __nv_bfloat16* Blo = (MODE == 1) ? g_w1lo : g_w2lo;
  float* C = (MODE == 1) ? g_h1 : g_h2lin;

  __shared__ __nv_bfloat16 Ah[BM][LDA], Al[BM][LDA];
  __shared__ __nv_bfloat16 Bh[BK][LDB], Bl[BK][LDB];

  const int tid = threadIdx.x;
  const int wid = tid >> 5;
  const int wr = wid >> 1, wc = wid & 1;        // warp grid 4 x 2
  const int bm = blockIdx.x * BM;
  const int bn = blockIdx.y * BN;

  wmma::fragment<wmma::accumulator, 16, 16, 16, float> acc[2][NJ];
#pragma unroll
  for (int i = 0; i < 2; i++)
#pragma unroll
    for (int j = 0; j < NJ; j++) wmma::fill_fragment(acc[i][j], 0.f);

  for (int k0 = 0; k0 < K; k0 += BK) {
    // load A tile (BM x BK hi/lo), 8 bf16 per thread-vec
#pragma unroll
    for (int it = 0; it < 2; it++) {
      int v = it * 256 + tid;              // 0..511
      int r = v >> 2, c8 = (v & 3) << 3;   // row, col*8
      int gr = bm + r;
      uint4 vh = make_uint4(0, 0, 0, 0), vl = make_uint4(0, 0, 0, 0);
      if (gr < NN) {
        size_t go = (size_t)gr * K + k0 + c8;
        vh = __ldg((const uint4*)(Ahi + go));
        vl = __ldg((const uint4*)(Alo + go));
      }
      *(uint4*)&Ah[r][c8] = vh;
      *(uint4*)&Al[r][c8] = vl;
    }
    // load B tile (BK x BN hi/lo)
    constexpr int BV = BK * BN / 8;        // 512 or 256 vec loads
#pragma unroll
    for (int it = 0; it < BV / 256; it++) {
      int v = it * 256 + tid;
      int r = v / (BN / 8), c8 = (v % (BN / 8)) << 3;
      size_t go = (size_t)(k0 + r) * NC + bn + c8;
      *(uint4*)&Bh[r][c8] = __ldg((const uint4*)(Bhi + go));
      *(uint4*)&Bl[r][c8] = __ldg((const uint4*)(Blo + go));
    }
    __syncthreads();

#pragma unroll
    for (int kk = 0; kk < BK; kk += 16) {
      wmma::fragment<wmma::matrix_a, 16, 16, 16, __nv_bfloat16, wmma::row_major> fah[2], fal[2];
      wmma::fragment<wmma::matrix_b, 16, 16, 16, __nv_bfloat16, wmma::row_major> fbh[NJ], fbl[NJ];
#pragma unroll
      for (int i = 0; i < 2; i++) {
        wmma::load_matrix_sync(fah[i], &Ah[wr * 32 + i * 16][kk], LDA);
        wmma::load_matrix_sync(fal[i], &Al[wr * 32 + i * 16][kk], LDA);
      }
#pragma unroll
      for (int j = 0; j < NJ; j++) {
        wmma::load_matrix_sync(fbh[j], &Bh[kk][wc * NJ * 16 + j * 16], LDB);
        wmma::load_matrix_sync(fbl[j], &Bl[kk][wc * NJ * 16 + j * 16], LDB);
      }
#pragma unroll
      for (int i = 0; i < 2; i++)
#pragma unroll
        for (int j = 0; j < NJ; j++) {
          wmma::mma_sync(acc[i][j], fah[i], fbh[j], acc[i][j]);
          wmma::mma_sync(acc[i][j], fah[i], fbl[j], acc[i][j]);
          wmma::mma_sync(acc[i][j], fal[i], fbh[j], acc[i][j]);
        }
    }
    __syncthreads();
  }

#pragma unroll
  for (int i = 0; i < 2; i++) {
    int r0 = bm + wr * 32 + i * 16;
    if (r0 < NN) {   // NN % 16 == 0, so whole fragment is in range
#pragma unroll
      for (int j = 0; j < NJ; j++)
        wmma::store_matrix_sync(&C[(size_t)r0 * NC + bn + wc * NJ * 16 + j * 16],
                                acc[i][j], NC, wmma::mem_row_major);
    }
  }
}

// ---------------- attention logits -------------------------------------------
__global__ __launch_bounds__(256) void k_al1(const float* __restrict__ a_src,
                                             const float* __restrict__ a_dst) {
  int w = (blockIdx.x * 256 + threadIdx.x) >> 5;
  int lane = threadIdx.x & 31;
  if (w >= NN) return;
  const float4* hp = (const float4*)(g_h1 + (size_t)w * C1 + (lane << 3));
  float4 h0 = hp[0], h1 = hp[1];
  const float4* sp = (const float4*)(a_src + (lane << 3));
  const float4* dp = (const float4*)(a_dst + (lane << 3));
  float4 s0 = __ldg(sp), s1 = __ldg(sp + 1);
  float4 d0 = __ldg(dp), d1 = __ldg(dp + 1);
  float ss = h0.x * s0.x + h0.y * s0.y + h0.z * s0.z + h0.w * s0.w +
             h1.x * s1.x + h1.y * s1.y + h1.z * s1.z + h1.w * s1.w;
  float dd = h0.x * d0.x + h0.y * d0.y + h0.z * d0.z + h0.w * d0.w +
             h1.x * d1.x + h1.y * d1.y + h1.z * d1.z + h1.w * d1.w;
#pragma unroll
  for (int o = 1; o < 8; o <<= 1) {
    ss += __shfl_xor_sync(0xffffffffu, ss, o);
    dd += __shfl_xor_sync(0xffffffffu, dd, o);
  }
  if ((lane & 7) == 0) {
    int hd = lane >> 3;
    g_als1[w * 4 + hd] = ss;
    g_ald1[w * 4 + hd] = dd;
  }
}

__global__ __launch_bounds__(256) void k_al2(const float* __restrict__ a_src,
                                             const float* __restrict__ a_dst) {
  int w = (blockIdx.x * 256 + threadIdx.x) >> 5;
  int lane = threadIdx.x & 31;
  if (w >= NN) return;
  int c = lane << 1;
  float2 h = *(const float2*)(g_h2lin + (size_t)w * C2 + c);
  float ss = h.x * __ldg(a_src + c) + h.y * __ldg(a_src + c + 1);
  float dd = h.x * __ldg(a_dst + c) + h.y * __ldg(a_dst + c + 1);
#pragma unroll
  for (int o = 16; o; o >>= 1) {
    ss += __shfl_xor_sync(0xffffffffu, ss, o);
    dd += __shfl_xor_sync(0xffffffffu, dd, o);
  }
  if (lane == 0) {
    g_als2[w] = ss;
    g_ald2[w] = dd;
  }
}

// ---------------- layer1 aggregation: warp per dst node ----------------------
__global__ __launch_bounds__(256) void k_agg1(const float* __restrict__ b1) {
  int w = (blockIdx.x * 256 + threadIdx.x) >> 5;
  int lane = threadIdx.x & 31;
  if (w >= NN) return;
  const int node = w;
  const int off = g_off[node], end = g_off[node + 1];
  float4 ad = *(const float4*)&g_ald1[node * 4];

  float m0 = -3e38f, m1 = -3e38f, m2 = -3e38f, m3 = -3e38f;
  for (int j = off + lane; j < end; j += 32) {
    int s = g_psrc[j];
    float4 as = __ldg((const float4*)&g_als1[s * 4]);
    m0 = fmaxf(m0, lrelu(as.x + ad.x));
    m1 = fmaxf(m1, lrelu(as.y + ad.y));
    m2 = fmaxf(m2, lrelu(as.z + ad.z));
    m3 = fmaxf(m3, lrelu(as.w + ad.w));
  }
#pragma unroll
  for (int o = 16; o; o >>= 1) {
    m0 = fmaxf(m0, __shfl_xor_sync(0xffffffffu, m0, o));
    m1 = fmaxf(m1, __shfl_xor_sync(0xffffffffu, m1, o));
    m2 = fmaxf(m2, __shfl_xor_sync(0xffffffffu, m2, o));
    m3 = fmaxf(m3, __shfl_xor_sync(0xffffffffu, m3, o));
  }
  float s0 = 0.f, s1 = 0.f, s2 = 0.f, s3 = 0.f;
  for (int j = off + lane; j < end; j += 32) {
    int s = g_psrc[j];
    float4 as = __ldg((const float4*)&g_als1[s * 4]);
    s0 += __expf(lrelu(as.x + ad.x) - m0);
    s1 += __expf(lrelu(as.y + ad.y) - m1);
    s2 += __expf(lrelu(as.z + ad.z) - m2);
    s3 += __expf(lrelu(as.w + ad.w) - m3);
  }
#pragma unroll
  for (int o = 16; o; o >>= 1) {
    s0 += __shfl_xor_sync(0xffffffffu, s0, o);
    s1 += __shfl_xor_sync(0xffffffffu, s1, o);
    s2 += __shfl_xor_sync(0xffffffffu, s2, o);
    s3 += __shfl_xor_sync(0xffffffffu, s3, o);
  }
  const int hd = lane >> 3;
  float mh = hd == 0 ? m0 : hd == 1 ? m1 : hd == 2 ? m2 : m3;
  float sh = hd == 0 ? s0 : hd == 1 ? s1 : hd == 2 ? s2 : s3;
  float adh = hd == 0 ? ad.x : hd == 1 ? ad.y : hd == 2 ? ad.z : ad.w;
  float inv = 1.f / (sh + 1e-16f);

  float acc[8] = {0.f, 0.f, 0.f, 0.f, 0.f, 0.f, 0.f, 0.f};
  const int myc = lane << 3;
  for (int j = off; j < end; j++) {
    int s = g_psrc[j];
    float asv = __ldg(&g_als1[s * 4 + hd]);
    float alpha = __expf(lrelu(asv + adh) - mh) * inv;
    const float4* hp = (const float4*)(g_h1 + (size_t)s * C1 + myc);
    float4 p = __ldg(hp), q = __ldg(hp + 1);
    acc[0] += p.x * alpha; acc[1] += p.y * alpha;
    acc[2] += p.z * alpha; acc[3] += p.w * alpha;
    acc[4] += q.x * alpha; acc[5] += q.y * alpha;
    acc[6] += q.z * alpha; acc[7] += q.w * alpha;
  }
  float4 bb0 = __ldg((const float4*)&b1[myc]);
  float4 bb1 = __ldg((const float4*)&b1[myc + 4]);
  float vo[8];
  vo[0] = elu_f(acc[0] + bb0.x); vo[1] = elu_f(acc[1] + bb0.y);
  vo[2] = elu_f(acc[2] + bb0.z); vo[3] = elu_f(acc[3] + bb0.w);
  vo[4] = elu_f(acc[4] + bb1.x); vo[5] = elu_f(acc[5] + bb1.y);
  vo[6] = elu_f(acc[6] + bb1.z); vo[7] = elu_f(acc[7] + bb1.w);
  // emit h2 as bf16 hi/lo (feeds layer2 tensor GEMM)
  union Pk { __nv_bfloat16 h[8]; uint4 u; } ph, pl;
#pragma unroll
  for (int e = 0; e < 8; e++) {
    ph.h[e] = __float2bfloat16(vo[e]);
    pl.h[e] = __float2bfloat16(vo[e] - __bfloat162float(ph.h[e]));
  }
  *(uint4*)&g_h2hi[(size_t)node * C1 + myc] = ph.u;
  *(uint4*)&g_h2lo[(size_t)node * C1 + myc] = pl.u;
}

// ---------------- layer2 aggregation: warp per dst node ----------------------
__global__ __launch_bounds__(256) void k_agg2(const float* __restrict__ b2,
                                              float* __restrict__ out) {
  int w = (blockIdx.x * 256 + threadIdx.x) >> 5;
  int lane = threadIdx.x & 31;
  if (w >= NN) return;
  const int node = w;
  const int off = g_off[node], end = g_off[node + 1];
  float ad = g_ald2[node];

  float m = -3e38f;
  for (int j = off + lane; j < end; j += 32) {
    int s = g_psrc[j];
    m = fmaxf(m, lrelu(__ldg(&g_als2[s]) + ad));
  }
#pragma unroll
  for (int o = 16; o; o >>= 1) m = fmaxf(m, __shfl_xor_sync(0xffffffffu, m, o));
  float su = 0.f;
  for (int j = off + lane; j < end; j += 32) {
    int s = g_psrc[j];
    su += __expf(lrelu(__ldg(&g_als2[s]) + ad) - m);
  }
#pragma unroll
  for (int o = 16; o; o >>= 1) su += __shfl_xor_sync(0xffffffffu, su, o);
  float inv = 1.f / (su + 1e-16f);

  float a0 = 0.f, a1 = 0.f;
  const int c = lane << 1;
  for (int j = off; j < end; j++) {
    int s = g_psrc[j];
    float alpha = __expf(lrelu(__ldg(&g_als2[s]) + ad) - m) * inv;
    float2 p = __ldg((const float2*)(g_h2lin + (size_t)s * C2 + c));
    a0 += p.x * alpha;
    a1 += p.y * alpha;
  }
  float2 r;
  r.x = elu_f(a0 + __ldg(&b2[c]));
  r.y = elu_f(a1 + __ldg(&b2[c + 1]));
  *(float2*)(out + (size_t)node * C2 + c) = r;
}

// ---------------- launch ------------------------------------------------------
extern "C" void kernel_launch(void* const* d_in, const int* in_sizes, int n_in,
                              void* d_out, int out_size) {
  const float* x = (const float*)d_in[0];
  const int* ei = (const int*)d_in[1];
  const float* W1 = (const float*)d_in[2];
  const float* as1 = (const float*)d_in[3];
  const float* ad1 = (const float*)d_in[4];
  const float* b1 = (const float*)d_in[5];
  const float* W2 = (const float*)d_in[6];
  const float* as2 = (const float*)d_in[7];
  const float* ad2 = (const float*)d_in[8];
  const float* b2 = (const float*)d_in[9];
  float* out = (float*)d_out;

  const int NB = (NN + 255) / 256;  // 196

  // CSR build (by dst, self loop in first slot)
  k_hist<<<(EE + 255) / 256, 256>>>(ei);
  k_scan1<<<NB, 256>>>();
  k_scan2<<<1, 256>>>();
  k_scan3<<<NB, 256>>>();
  k_scatter<<<(EE + 255) / 256, 256>>>(ei);

  // operand conversions
  k_cvt_x<<<(NN * 128 / 4 + 255) / 256, 256>>>(x);
  k_cvt_w<<<(128 * 256 + 255) / 256, 256>>>(W1, W2);

  const int NT = (NN + 127) / 128;  // 391 row tiles
  // layer 1
  dim3 g1(NT, C1 / 128);
  k_wgemm<1><<<g1, 256>>>();
  int nwb = (NN * 32 + 255) / 256;  // warp per node
  k_al1<<<nwb, 256>>>(as1, ad1);
  k_agg1<<<nwb, 256>>>(b1);

  // layer 2
  dim3 g2(NT, 1);
  k_wgemm<2><<<g2, 256>>>();
  k_al2<<<nwb, 256>>>(as2, ad2);
  k_agg2<<<nwb, 256>>>(b2, out);
}

// round 7
// speedup vs baseline: 1.5533x; 1.0853x over previous
#include <cuda_runtime.h>
#include <cuda_bf16.h>
#include <mma.h>
#include <cstdint>

using namespace nvcuda;

#define NN 50000
#define EE 800000
#define ET (EE + NN)
#define HEADS 4
#define HID 64
#define C1 256   /* HEADS*HID */
#define C2 64
#define NEG 0.2f

// ---------------- scratch (device globals; no cudaMalloc allowed) -------------
__device__ __align__(16) float g_h1[(size_t)NN * C1];
__device__ __align__(16) float g_als1[NN * HEADS];
__device__ __align__(16) float g_ald1[NN * HEADS];
__device__ __align__(16) float g_h2lin[(size_t)NN * C2];
__device__ float g_als2[NN];
__device__ float g_ald2[NN];
__device__ int   g_cnt[NN];
__device__ int   g_off[NN + 1];
__device__ int   g_cur[NN];
__device__ int   g_psrc[ET];
__device__ int   g_bsum[256];
__device__ __align__(16) __nv_bfloat16 g_xhi[(size_t)NN * 128];
__device__ __align__(16) __nv_bfloat16 g_xlo[(size_t)NN * 128];
__device__ __align__(16) __nv_bfloat16 g_h2hi[(size_t)NN * C1];
__device__ __align__(16) __nv_bfloat16 g_h2lo[(size_t)NN * C1];
__device__ __align__(16) __nv_bfloat16 g_w1hi[128 * C1];   // [k=128][n=256]
__device__ __align__(16) __nv_bfloat16 g_w1lo[128 * C1];
__device__ __align__(16) __nv_bfloat16 g_w2hi[C1 * C2];    // [k=256][n=64]
__device__ __align__(16) __nv_bfloat16 g_w2lo[C1 * C2];

__device__ __forceinline__ float lrelu(float x) { return x > 0.f ? x : NEG * x; }
__device__ __forceinline__ float elu_f(float x) { return x > 0.f ? x : __expf(x) - 1.f; }

__device__ __forceinline__ void cp16z(uint32_t d, const void* s, bool pred) {
  if (pred)
    asm volatile("cp.async.ca.shared.global [%0], [%1], 16;" :: "r"(d), "l"(s));
  else
    asm volatile("cp.async.ca.shared.global [%0], [%1], 16, 0;" :: "r"(d), "l"(s));
}
__device__ __forceinline__ void cpa_commit() {
  asm volatile("cp.async.commit_group;" ::: "memory");
}
template <int N>
__device__ __forceinline__ void cpa_wait() {
  asm volatile("cp.async.wait_group %0;" :: "n"(N) : "memory");
}

// ---------------- CSR build ---------------------------------------------------
__global__ void k_hist(const int* __restrict__ ei) {
  int e = blockIdx.x * blockDim.x + threadIdx.x;
  if (e < EE) atomicAdd(&g_cnt[ei[EE + e]], 1);
}

__global__ __launch_bounds__(256) void k_scan1() {
  int i = blockIdx.x * 256 + threadIdx.x;
  int v = 0;
  if (i < NN) { v = g_cnt[i] + 1; g_cnt[i] = 0; }
  int lane = threadIdx.x & 31, wid = threadIdx.x >> 5;
  int x = v;
#pragma unroll
  for (int o = 1; o < 32; o <<= 1) {
    int y = __shfl_up_sync(0xffffffffu, x, o);
    if (lane >= o) x += y;
  }
  __shared__ int ws[8];
  if (lane == 31) ws[wid] = x;
  __syncthreads();
  if (threadIdx.x < 8) {
    int z = ws[threadIdx.x];
#pragma unroll
    for (int o = 1; o < 8; o <<= 1) {
      int q = __shfl_up_sync(0xffu, z, o);
      if ((int)threadIdx.x >= o) z += q;
    }
    ws[threadIdx.x] = z;
  }
  __syncthreads();
  int incl = x + (wid ? ws[wid - 1] : 0);
  if (i < NN) g_off[i] = incl - v;
  if (threadIdx.x == 255) g_bsum[blockIdx.x] = incl;
}

__global__ __launch_bounds__(256) void k_scan2() {
  const int NB = (NN + 255) / 256;
  int t = threadIdx.x;
  int v = (t < NB) ? g_bsum[t] : 0;
  int lane = t & 31, wid = t >> 5;
  int x = v;
#pragma unroll
  for (int o = 1; o < 32; o <<= 1) {
    int y = __shfl_up_sync(0xffffffffu, x, o);
    if (lane >= o) x += y;
  }
  __shared__ int ws[8];
  if (lane == 31) ws[wid] = x;
  __syncthreads();
  if (t < 8) {
    int z = ws[t];
#pragma unroll
    for (int o = 1; o < 8; o <<= 1) {
      int q = __shfl_up_sync(0xffu, z, o);
      if (t >= o) z += q;
    }
    ws[t] = z;
  }
  __syncthreads();
  int incl = x + (wid ? ws[wid - 1] : 0);
  if (t < NB) g_bsum[t] = incl - v;
}

__global__ void k_scan3() {
  int i = blockIdx.x * blockDim.x + threadIdx.x;
  if (i < NN) {
    int o = g_off[i] + g_bsum[i >> 8];
    g_off[i] = o;
    g_psrc[o] = i;
    g_cur[i] = o + 1;
  }
  if (i == 0) g_off[NN] = ET;
}

__global__ void k_scatter(const int* __restrict__ ei) {
  int e = blockIdx.x * blockDim.x + threadIdx.x;
  if (e < EE) {
    int s = ei[e];
    int d = ei[EE + e];
    g_psrc[atomicAdd(&g_cur[d], 1)] = s;
  }
}

// ---------------- fp32 -> bf16 hi/lo conversions -------------------------------
__global__ void k_cvt_x(const float* __restrict__ x) {
  int i = blockIdx.x * blockDim.x + threadIdx.x;
  const int n4 = NN * 128 / 4;
  if (i >= n4) return;
  float4 v = __ldg((const float4*)x + i);
  float vv[4] = {v.x, v.y, v.z, v.w};
  __nv_bfloat16 h[4], l[4];
#pragma unroll
  for (int q = 0; q < 4; q++) {
    h[q] = __float2bfloat16(vv[q]);
    l[q] = __float2bfloat16(vv[q] - __bfloat162float(h[q]));
  }
  ((__nv_bfloat162*)g_xhi)[2 * i]     = __nv_bfloat162(h[0], h[1]);
  ((__nv_bfloat162*)g_xhi)[2 * i + 1] = __nv_bfloat162(h[2], h[3]);
  ((__nv_bfloat162*)g_xlo)[2 * i]     = __nv_bfloat162(l[0], l[1]);
  ((__nv_bfloat162*)g_xlo)[2 * i + 1] = __nv_bfloat162(l[2], l[3]);
}

__global__ void k_cvt_w(const float* __restrict__ W1,
                        const float* __restrict__ W2) {
  int i = blockIdx.x * blockDim.x + threadIdx.x;
  if (i < 128 * 256) {
    float v = __ldg(&W1[i]);
    __nv_bfloat16 h = __float2bfloat16(v);
    g_w1hi[i] = h;
    g_w1lo[i] = __float2bfloat16(v - __bfloat162float(h));
  }
  if (i < 256 * 64) {
    float v = __ldg(&W2[i]);
    __nv_bfloat16 h = __float2bfloat16(v);
    g_w2hi[i] = h;
    g_w2lo[i] = __float2bfloat16(v - __bfloat162float(h));
  }
}

// ---------------- wmma bf16 split-precision GEMM, cp.async 2-stage -------------
// MODE 1: g_h1[NN,256] = x @ W1 (K=128, BN=128, grid.y=2)
// MODE 2: g_h2lin[NN,64] = h2 @ W2 (K=256, BN=64)
template <int MODE>
__global__ __launch_bounds__(256) void k_wgemm() {
  constexpr int K  = (MODE == 1) ? 128 : 256;
  constexpr int NC = (MODE == 1) ? 256 : 64;
  constexpr int BN = (MODE == 1) ? 128 : 64;
  constexpr int BM = 128, BK = 32;
  constexpr int KT = K / BK;
  constexpr int LDA = 48;          // 96B rows, 16B multiple
  constexpr int LDB = BN + 16;     // 288B / 160B rows
  constexpr int NJ = BN / 32;
  constexpr int ASTG = BM * LDA;   // elems per A stage
  constexpr int BSTG = BK * LDB;

  extern __shared__ __nv_bfloat16 sm[];
  __nv_bfloat16* Ah = sm;                    // [2][BM][LDA]
  __nv_bfloat16* Al = Ah + 2 * ASTG;
  __nv_bfloat16* Bh = Al + 2 * ASTG;         // [2][BK][LDB]
  __nv_bfloat16* Bl = Bh + 2 * BSTG;

  const __nv_bfloat16* Ahi = (MODE == 1) ? g_xhi : g_h2hi;
  const __nv_bfloat16* Alo = (MODE == 1) ? g_xlo : g_h2lo;
  const __nv_bfloat16* Bhi = (MODE == 1) ? g_w1hi : g_w2hi;
  const __nv_bfloat16* Blo = (MODE == 1) ? g_w1lo : g_w2lo;
  float* C = (MODE == 1) ? g_h1 : g_h2lin;

  const int tid = threadIdx.x;
  const int wid = tid >> 5;
  const int wr = wid >> 1, wc = wid & 1;
  const int bm = blockIdx.x * BM;
  const int bn = blockIdx.y * BN;

  auto loadA = [&](int kt, int st) {
#pragma unroll
    for (int it = 0; it < 2; it++) {
      int v = it * 256 + tid;            // 0..511
      int r = v >> 2, c8 = (v & 3) << 3;
      int gr = bm + r;
      bool ok = gr < NN;
      size_t go = (size_t)(ok ? gr : 0) * K + kt * BK + c8;
      int so = st * ASTG + r * LDA + c8;
      cp16z((uint32_t)__cvta_generic_to_shared(&Ah[so]), Ahi + go, ok);
      cp16z((uint32_t)__cvta_generic_to_shared(&Al[so]), Alo + go, ok);
    }
  };
  auto loadB = [&](int kt, int st) {
    constexpr int NV = BK * BN / 8;      // 512 or 256
#pragma unroll
    for (int it = 0; it < NV / 256; it++) {
      int v = it * 256 + tid;
      int r = v / (BN / 8), c8 = (v % (BN / 8)) << 3;
      size_t go = (size_t)(kt * BK + r) * NC + bn + c8;
      int so = st * BSTG + r * LDB + c8;
      cp16z((uint32_t)__cvta_generic_to_shared(&Bh[so]), Bhi + go, true);
      cp16z((uint32_t)__cvta_generic_to_shared(&Bl[so]), Blo + go, true);
    }
  };

  wmma::fragment<wmma::accumulator, 16, 16, 16, float> acc[2][NJ];
#pragma unroll
  for (int i = 0; i < 2; i++)
#pragma unroll
    for (int j = 0; j < NJ; j++) wmma::fill_fragment(acc[i][j], 0.f);

  loadA(0, 0); loadB(0, 0); cpa_commit();

#pragma unroll
  for (int kt = 0; kt < KT; kt++) {
    const int cur = kt & 1;
    if (kt + 1 < KT) { loadA(kt + 1, cur ^ 1); loadB(kt + 1, cur ^ 1); cpa_commit(); }
    if (kt + 1 < KT) cpa_wait<1>(); else cpa_wait<0>();
    __syncthreads();
#pragma unroll
    for (int kk = 0; kk < BK; kk += 16) {
      wmma::fragment<wmma::matrix_a, 16, 16, 16, __nv_bfloat16, wmma::row_major> fah[2], fal[2];
      wmma::fragment<wmma::matrix_b, 16, 16, 16, __nv_bfloat16, wmma::row_major> fbh[NJ], fbl[NJ];
#pragma unroll
      for (int i = 0; i < 2; i++) {
        wmma::load_matrix_sync(fah[i], &Ah[cur * ASTG + (wr * 32 + i * 16) * LDA + kk], LDA);
        wmma::load_matrix_sync(fal[i], &Al[cur * ASTG + (wr * 32 + i * 16) * LDA + kk], LDA);
      }
#pragma unroll
      for (int j = 0; j < NJ; j++) {
        wmma::load_matrix_sync(fbh[j], &Bh[cur * BSTG + kk * LDB + wc * NJ * 16 + j * 16], LDB);
        wmma::load_matrix_sync(fbl[j], &Bl[cur * BSTG + kk * LDB + wc * NJ * 16 + j * 16], LDB);
      }
#pragma unroll
      for (int i = 0; i < 2; i++)
#pragma unroll
        for (int j = 0; j < NJ; j++) {
          wmma::mma_sync(acc[i][j], fah[i], fbh[j], acc[i][j]);
          wmma::mma_sync(acc[i][j], fah[i], fbl[j], acc[i][j]);
          wmma::mma_sync(acc[i][j], fal[i], fbh[j], acc[i][j]);
        }
    }
    __syncthreads();
  }

#pragma unroll
  for (int i = 0; i < 2; i++) {
    int r0 = bm + wr * 32 + i * 16;
    if (r0 < NN) {
#pragma unroll
      for (int j = 0; j < NJ; j++)
        wmma::store_matrix_sync(&C[(size_t)r0 * NC + bn + wc * NJ * 16 + j * 16],
                                acc[i][j], NC, wmma::mem_row_major);
    }
  }
}

// ---------------- attention logits -------------------------------------------
__global__ __launch_bounds__(256) void k_al1(const float* __restrict__ a_src,
                                             const float* __restrict__ a_dst) {
  int w = (blockIdx.x * 256 + threadIdx.x) >> 5;
  int lane = threadIdx.x & 31;
  if (w >= NN) return;
  const float4* hp = (const float4*)(g_h1 + (size_t)w * C1 + (lane << 3));
  float4 h0 = hp[0], h1 = hp[1];
  const float4* sp = (const float4*)(a_src + (lane << 3));
  const float4* dp = (const float4*)(a_dst + (lane << 3));
  float4 s0 = __ldg(sp), s1 = __ldg(sp + 1);
  float4 d0 = __ldg(dp), d1 = __ldg(dp + 1);
  float ss = h0.x * s0.x + h0.y * s0.y + h0.z * s0.z + h0.w * s0.w +
             h1.x * s1.x + h1.y * s1.y + h1.z * s1.z + h1.w * s1.w;
  float dd = h0.x * d0.x + h0.y * d0.y + h0.z * d0.z + h0.w * d0.w +
             h1.x * d1.x + h1.y * d1.y + h1.z * d1.z + h1.w * d1.w;
#pragma unroll
  for (int o = 1; o < 8; o <<= 1) {
    ss += __shfl_xor_sync(0xffffffffu, ss, o);
    dd += __shfl_xor_sync(0xffffffffu, dd, o);
  }
  if ((lane & 7) == 0) {
    int hd = lane >> 3;
    g_als1[w * 4 + hd] = ss;
    g_ald1[w * 4 + hd] = dd;
  }
}

__global__ __launch_bounds__(256) void k_al2(const float* __restrict__ a_src,
                                             const float* __restrict__ a_dst) {
  int w = (blockIdx.x * 256 + threadIdx.x) >> 5;
  int lane = threadIdx.x & 31;
  if (w >= NN) return;
  int c = lane << 1;
  float2 h = *(const float2*)(g_h2lin + (size_t)w * C2 + c);
  float ss = h.x * __ldg(a_src + c) + h.y * __ldg(a_src + c + 1);
  float dd = h.x * __ldg(a_dst + c) + h.y * __ldg(a_dst + c + 1);
#pragma unroll
  for (int o = 16; o; o >>= 1) {
    ss += __shfl_xor_sync(0xffffffffu, ss, o);
    dd += __shfl_xor_sync(0xffffffffu, dd, o);
  }
  if (lane == 0) {
    g_als2[w] = ss;
    g_ald2[w] = dd;
  }
}

// ---------------- layer1 aggregation: warp per dst node ----------------------
__global__ __launch_bounds__(256) void k_agg1(const float* __restrict__ b1) {
  int w = (blockIdx.x * 256 + threadIdx.x) >> 5;
  int lane = threadIdx.x & 31;
  if (w >= NN) return;
  const int node = w;
  const int off = g_off[node], end = g_off[node + 1];
  float4 ad = *(const float4*)&g_ald1[node * 4];

  float m0 = -3e38f, m1 = -3e38f, m2 = -3e38f, m3 = -3e38f;
  for (int j = off + lane; j < end; j += 32) {
    int s = g_psrc[j];
    float4 as = __ldg((const float4*)&g_als1[s * 4]);
    m0 = fmaxf(m0, lrelu(as.x + ad.x));
    m1 = fmaxf(m1, lrelu(as.y + ad.y));
    m2 = fmaxf(m2, lrelu(as.z + ad.z));
    m3 = fmaxf(m3, lrelu(as.w + ad.w));
  }
#pragma unroll
  for (int o = 16; o; o >>= 1) {
    m0 = fmaxf(m0, __shfl_xor_sync(0xffffffffu, m0, o));
    m1 = fmaxf(m1, __shfl_xor_sync(0xffffffffu, m1, o));
    m2 = fmaxf(m2, __shfl_xor_sync(0xffffffffu, m2, o));
    m3 = fmaxf(m3, __shfl_xor_sync(0xffffffffu, m3, o));
  }
  float s0 = 0.f, s1 = 0.f, s2 = 0.f, s3 = 0.f;
  for (int j = off + lane; j < end; j += 32) {
    int s = g_psrc[j];
    float4 as = __ldg((const float4*)&g_als1[s * 4]);
    s0 += __expf(lrelu(as.x + ad.x) - m0);
    s1 += __expf(lrelu(as.y + ad.y) - m1);
    s2 += __expf(lrelu(as.z + ad.z) - m2);
    s3 += __expf(lrelu(as.w + ad.w) - m3);
  }
#pragma unroll
  for (int o = 16; o; o >>= 1) {
    s0 += __shfl_xor_sync(0xffffffffu, s0, o);
    s1 += __shfl_xor_sync(0xffffffffu, s1, o);
    s2 += __shfl_xor_sync(0xffffffffu, s2, o);
    s3 += __shfl_xor_sync(0xffffffffu, s3, o);
  }
  const int hd = lane >> 3;
  float mh = hd == 0 ? m0 : hd == 1 ? m1 : hd == 2 ? m2 : m3;
  float sh = hd == 0 ? s0 : hd == 1 ? s1 : hd == 2 ? s2 : s3;
  float adh = hd == 0 ? ad.x : hd == 1 ? ad.y : hd == 2 ? ad.z : ad.w;
  float inv = 1.f / (sh + 1e-16f);

  float acc[8] = {0.f, 0.f, 0.f, 0.f, 0.f, 0.f, 0.f, 0.f};
  const int myc = lane << 3;
  for (int j = off; j < end; j++) {
    int s = g_psrc[j];
    float asv = __ldg(&g_als1[s * 4 + hd]);
    float alpha = __expf(lrelu(asv + adh) - mh) * inv;
    const float4* hp = (const float4*)(g_h1 + (size_t)s * C1 + myc);
    float4 p = __ldg(hp), q = __ldg(hp + 1);
    acc[0] += p.x * alpha; acc[1] += p.y * alpha;
    acc[2] += p.z * alpha; acc[3] += p.w * alpha;
    acc[4] += q.x * alpha; acc[5] += q.y * alpha;
    acc[6] += q.z * alpha; acc[7] += q.w * alpha;
  }
  float4 bb0 = __ldg((const float4*)&b1[myc]);
  float4 bb1 = __ldg((const float4*)&b1[myc + 4]);
  float vo[8];
  vo[0] = elu_f(acc[0] + bb0.x); vo[1] = elu_f(acc[1] + bb0.y);
  vo[2] = elu_f(acc[2] + bb0.z); vo[3] = elu_f(acc[3] + bb0.w);
  vo[4] = elu_f(acc[4] + bb1.x); vo[5] = elu_f(acc[5] + bb1.y);
  vo[6] = elu_f(acc[6] + bb1.z); vo[7] = elu_f(acc[7] + bb1.w);
  union Pk { __nv_bfloat16 h[8]; uint4 u; } ph, pl;
#pragma unroll
  for (int e = 0; e < 8; e++) {
    ph.h[e] = __float2bfloat16(vo[e]);
    pl.h[e] = __float2bfloat16(vo[e] - __bfloat162float(ph.h[e]));
  }
  *(uint4*)&g_h2hi[(size_t)node * C1 + myc] = ph.u;
  *(uint4*)&g_h2lo[(size_t)node * C1 + myc] = pl.u;
}

// ---------------- layer2 aggregation: warp per dst node ----------------------
__global__ __launch_bounds__(256) void k_agg2(const float* __restrict__ b2,
                                              float* __restrict__ out) {
  int w = (blockIdx.x * 256 + threadIdx.x) >> 5;
  int lane = threadIdx.x & 31;
  if (w >= NN) return;
  const int node = w;
  const int off = g_off[node], end = g_off[node + 1];
  float ad = g_ald2[node];

  float m = -3e38f;
  for (int j = off + lane; j < end; j += 32) {
    int s = g_psrc[j];
    m = fmaxf(m, lrelu(__ldg(&g_als2[s]) + ad));
  }
#pragma unroll
  for (int o = 16; o; o >>= 1) m = fmaxf(m, __shfl_xor_sync(0xffffffffu, m, o));
  float su = 0.f;
  for (int j = off + lane; j < end; j += 32) {
    int s = g_psrc[j];
    su += __expf(lrelu(__ldg(&g_als2[s]) + ad) - m);
  }
#pragma unroll
  for (int o = 16; o; o >>= 1) su += __shfl_xor_sync(0xffffffffu, su, o);
  float inv = 1.f / (su + 1e-16f);

  float a0 = 0.f, a1 = 0.f;
  const int c = lane << 1;
  for (int j = off; j < end; j++) {
    int s = g_psrc[j];
    float alpha = __expf(lrelu(__ldg(&g_als2[s]) + ad) - m) * inv;
    float2 p = __ldg((const float2*)(g_h2lin + (size_t)s * C2 + c));
    a0 += p.x * alpha;
    a1 += p.y * alpha;
  }
  float2 r;
  r.x = elu_f(a0 + __ldg(&b2[c]));
  r.y = elu_f(a1 + __ldg(&b2[c + 1]));
  *(float2*)(out + (size_t)node * C2 + c) = r;
}

// ---------------- launch ------------------------------------------------------
extern "C" void kernel_launch(void* const* d_in, const int* in_sizes, int n_in,
                              void* d_out, int out_size) {
  const float* x = (const float*)d_in[0];
  const int* ei = (const int*)d_in[1];
  const float* W1 = (const float*)d_in[2];
  const float* as1 = (const float*)d_in[3];
  const float* ad1 = (const float*)d_in[4];
  const float* b1 = (const float*)d_in[5];
  const float* W2 = (const float*)d_in[6];
  const float* as2 = (const float*)d_in[7];
  const float* ad2 = (const float*)d_in[8];
  const float* b2 = (const float*)d_in[9];
  float* out = (float*)d_out;

  static cudaStream_t s_csr = nullptr;
  static cudaEvent_t ev_fork = nullptr, ev_join = nullptr;
  if (!s_csr) {
    cudaStreamCreateWithFlags(&s_csr, cudaStreamNonBlocking);
    cudaEventCreateWithFlags(&ev_fork, cudaEventDisableTiming);
    cudaEventCreateWithFlags(&ev_join, cudaEventDisableTiming);
  }

  // dynamic smem sizes for the pipelined GEMMs
  const int SMEM1 = (2 * 128 * 48 * 2 + 2 * 32 * (128 + 16) * 2) * 2;  // bytes
  const int SMEM2 = (2 * 128 * 48 * 2 + 2 * 32 * (64 + 16) * 2) * 2;
  cudaFuncSetAttribute(k_wgemm<1>, cudaFuncAttributeMaxDynamicSharedMemorySize, SMEM1);
  cudaFuncSetAttribute(k_wgemm<2>, cudaFuncAttributeMaxDynamicSharedMemorySize, SMEM2);

  const int NB = (NN + 255) / 256;  // 196
  const int NT = (NN + 127) / 128;  // 391

  // fork: CSR chain on side stream, overlapped with cvt+gemm1+al1
  cudaEventRecord(ev_fork, 0);
  cudaStreamWaitEvent(s_csr, ev_fork, 0);
  k_hist<<<(EE + 255) / 256, 256, 0, s_csr>>>(ei);
  k_scan1<<<NB, 256, 0, s_csr>>>();
  k_scan2<<<1, 256, 0, s_csr>>>();
  k_scan3<<<NB, 256, 0, s_csr>>>();
  k_scatter<<<(EE + 255) / 256, 256, 0, s_csr>>>(ei);
  cudaEventRecord(ev_join, s_csr);

  // main chain (capture stream)
  k_cvt_x<<<(NN * 128 / 4 + 255) / 256, 256>>>(x);
  k_cvt_w<<<(128 * 256 + 255) / 256, 256>>>(W1, W2);
  dim3 g1(NT, C1 / 128);
  k_wgemm<1><<<g1, 256, SMEM1>>>();
  int nwb = (NN * 32 + 255) / 256;
  k_al1<<<nwb, 256>>>(as1, ad1);

  // join: aggregation needs CSR
  cudaStreamWaitEvent(0, ev_join, 0);
  k_agg1<<<nwb, 256>>>(b1);

  // layer 2
  k_wgemm<2><<<NT, 256, SMEM2>>>();
  k_al2<<<nwb, 256>>>(as2, ad2);
  k_agg2<<<nwb, 256>>>(b2, out);
}